// round 10
// baseline (speedup 1.0000x reference)
#include <cuda_runtime.h>
#include <cuda_bf16.h>
#include <math.h>

#define H      512
#define WD     1024
#define VOCAB  30000
#define BATCH  64
#define SEQL   256
#define TSTEPS 27
#define GK     (WD + H)
#define G4H    2048
#define NT     3750              /* 8-col tiles: 30000/8 exactly */
#define GRID   148
#define GBLK   128               /* gates blocks */

typedef unsigned long long ull;
typedef unsigned int u32;

__device__ float g_h[BATCH * H];
__device__ float g_c[BATCH * H];
__device__ float g_ctx[BATCH * H];
__device__ float g_gctx[BATCH * G4H];
__device__ float g_scores[BATCH * SEQL];
__device__ float g_u[H], g_t2[H], g_v[H];
__device__ ull   g_arg[TSTEPS * BATCH];
__device__ ull   g_initArg[BATCH];
__device__ u32   g_Aswz[4 * 32 * 32 * 8];           /* 128KB A frags (hi|lo) */
__device__ u32   g_Bswz[(size_t)NT * 32 * 32 * 4];  /* B frags */
__device__ u32   g_barCnt;

__device__ __forceinline__ ull pack2(float x) {
    ull r; asm("mov.b64 %0, {%1, %1};" : "=l"(r) : "r"(__float_as_uint(x))); return r;
}
__device__ __forceinline__ ull pack2b(float a, float b) {
    ull r; asm("mov.b64 %0, {%1, %2};" : "=l"(r)
               : "r"(__float_as_uint(a)), "r"(__float_as_uint(b))); return r;
}
__device__ __forceinline__ void fma2(ull &acc, ull a, ull b) {
    asm("fma.rn.f32x2 %0, %1, %2, %0;" : "+l"(acc) : "l"(a), "l"(b));
}
__device__ __forceinline__ float lof(ull v) { return __uint_as_float((unsigned)v); }
__device__ __forceinline__ float hif(ull v) { return __uint_as_float((unsigned)(v >> 32)); }
__device__ __forceinline__ ull amax_key(float v, int n) {
    unsigned u = __float_as_uint(v);
    u = (u & 0x80000000u) ? ~u : (u | 0x80000000u);
    return ((ull)u << 32) | (ull)(0xFFFFFFFFu - (unsigned)n);
}
__device__ __forceinline__ ull umax_(ull a, ull b) { return a > b ? a : b; }
__device__ __forceinline__ float sigf(float x) { return 1.f / (1.f + expf(-x)); }
__device__ __forceinline__ unsigned short bf16bits(float x) {
    __nv_bfloat16 b = __float2bfloat16(x);
    return *(unsigned short*)&b;
}
__device__ __forceinline__ float bf16val(float x) {
    return __bfloat162float(__float2bfloat16(x));
}
__device__ __forceinline__ u32 packbf(float a, float b) {
    return (u32)bf16bits(a) | ((u32)bf16bits(b) << 16);
}
__device__ __forceinline__ void mma_bf16(float* d, const u32* a, u32 b0, u32 b1) {
    asm volatile("mma.sync.aligned.m16n8k16.row.col.f32.bf16.bf16.f32 "
                 "{%0,%1,%2,%3}, {%4,%5,%6,%7}, {%8,%9}, {%0,%1,%2,%3};"
                 : "+f"(d[0]), "+f"(d[1]), "+f"(d[2]), "+f"(d[3])
                 : "r"(a[0]), "r"(a[1]), "r"(a[2]), "r"(a[3]), "r"(b0), "r"(b1));
}

/* grid barrier: monotonic counter */
__device__ __forceinline__ void gsync(unsigned target) {
    __syncthreads();
    if (threadIdx.x == 0) {
        u32* cnt = &g_barCnt;
        asm volatile("fence.acq_rel.gpu;" ::: "memory");
        asm volatile("red.relaxed.gpu.add.u32 [%0], 1;" :: "l"(cnt) : "memory");
        unsigned v;
        do { asm volatile("ld.acquire.gpu.u32 %0, [%1];" : "=r"(v) : "l"(cnt) : "memory"); }
        while (v < target);
    }
    __syncthreads();
}

__global__ void bar_init() { g_barCnt = 0u; }

/* ---- one-time: Wout -> B fragments (hi/lo bf16) ---- */
__global__ void wout_swz(const float* __restrict__ Wout) {
    int gid = blockIdx.x * 256 + threadIdx.x;   /* NT*1024 threads */
    int lane = gid & 31, kt = (gid >> 5) & 31, nt = gid >> 10;
    int gr = lane >> 2, c = lane & 3;
    int n = nt * 8 + gr;
    int k0 = kt * 16 + c * 2;
    float w00 = Wout[(size_t)k0 * VOCAB + n];
    float w01 = Wout[(size_t)(k0 + 1) * VOCAB + n];
    float w10 = Wout[(size_t)(k0 + 8) * VOCAB + n];
    float w11 = Wout[(size_t)(k0 + 9) * VOCAB + n];
    uint4 v;
    v.x = packbf(w00, w01);
    v.y = packbf(w10, w11);
    v.z = packbf(w00 - bf16val(w00), w01 - bf16val(w01));
    v.w = packbf(w10 - bf16val(w10), w11 - bf16val(w11));
    *(uint4*)&g_Bswz[(size_t)gid * 4] = v;
}

/* ---- one-time: v chain, init ---- */
__global__ void precompute1(const float* __restrict__ ehs, const float* __restrict__ W1,
                            const float* __restrict__ W2, const float* __restrict__ W3,
                            const float* __restrict__ Wv) {
    int tid = threadIdx.x;
    for (int i = tid; i < BATCH * H; i += 512) { g_h[i] = ehs[i]; g_c[i] = 0.f; }
    for (int i = tid; i < TSTEPS * BATCH; i += 512) g_arg[i] = 0ull;
    if (tid < BATCH) g_initArg[tid] = (ull)(0xFFFFFFFFu - 1u);
    float acc = 0.f;
#pragma unroll 8
    for (int j = 0; j < H; j++) acc += W3[tid * H + j] * Wv[j];
    g_u[tid] = acc; __syncthreads();
    acc = 0.f;
#pragma unroll 8
    for (int j = 0; j < H; j++) acc += W2[tid * H + j] * g_u[j];
    g_t2[tid] = acc; __syncthreads();
    acc = 0.f;
#pragma unroll 8
    for (int j = 0; j < H; j++) acc += W1[tid * H + j] * g_t2[j];
    g_v[tid] = acc;
}

__global__ void scores_kernel(const float* __restrict__ enc) {
    int tid = threadIdx.x;
    int g = blockIdx.x * 8 + (tid >> 5), lane = tid & 31;
    int b = g >> 8, s = g & 255;
    const float* e = enc + ((size_t)b * SEQL + s) * H;
    float acc = 0.f;
#pragma unroll
    for (int i = 0; i < 16; i++) acc += e[lane + i * 32] * g_v[lane + i * 32];
#pragma unroll
    for (int off = 16; off; off >>= 1) acc += __shfl_xor_sync(0xffffffffu, acc, off);
    if (lane == 0) g_scores[b * SEQL + s] = acc;
}

__global__ void softmax_ctx_kernel(const float* __restrict__ enc) {
    __shared__ float ss[SEQL], red[SEQL];
    int tid = threadIdx.x, b = blockIdx.x;
    if (tid < SEQL) { float v = g_scores[b * SEQL + tid]; ss[tid] = v; red[tid] = v; }
    __syncthreads();
    for (int s = 128; s > 0; s >>= 1) { if (tid < s) red[tid] = fmaxf(red[tid], red[tid + s]); __syncthreads(); }
    float mx = red[0]; __syncthreads();
    if (tid < SEQL) { float e = expf(ss[tid] - mx); ss[tid] = e; red[tid] = e; }
    __syncthreads();
    for (int s = 128; s > 0; s >>= 1) { if (tid < s) red[tid] += red[tid + s]; __syncthreads(); }
    float inv = 1.f / red[0]; __syncthreads();
    if (tid < SEQL) ss[tid] *= inv;
    __syncthreads();
    float acc = 0.f;
    const float* eb = enc + (size_t)b * SEQL * H + tid;
#pragma unroll 16
    for (int s = 0; s < SEQL; s++) acc += ss[s] * eb[(size_t)s * H];
    g_ctx[b * H + tid] = acc;
}

__global__ void gctx_kernel(const float* __restrict__ Wih, const float* __restrict__ bih,
                            const float* __restrict__ bhh) {
    __shared__ float ctxS[8][H];
    int tid = threadIdx.x;
    int jb = blockIdx.x & 7, bt = blockIdx.x >> 3;
    for (int i = tid; i < 8 * H; i += 256)
        ctxS[i >> 9][i & (H - 1)] = g_ctx[(bt * 8 + (i >> 9)) * H + (i & (H - 1))];
    __syncthreads();
    int j = jb * 256 + tid;
    float bj = bih[j] + bhh[j];
    float acc[8];
#pragma unroll
    for (int bb = 0; bb < 8; bb++) acc[bb] = bj;
#pragma unroll 8
    for (int k = 0; k < H; k++) {
        float w = Wih[(size_t)(WD + k) * G4H + j];
#pragma unroll
        for (int bb = 0; bb < 8; bb++) acc[bb] += ctxS[bb][k] * w;
    }
#pragma unroll
    for (int bb = 0; bb < 8; bb++) g_gctx[(bt * 8 + bb) * G4H + j] = acc[bb];
}

/* ---------------- persistent step loop ---------------- */
struct GSmem {                         /* gates+cell phase */
    float Asm[32][68];                 /* k x m, padded */
    float Bsm[16][44];                 /* n x k, padded */
    float Csm[64][16];                 /* m x n outputs */
    int   ciw[64];
};
struct LSmem {                         /* logits phase */
    u32 sA[4 * 32 * 32 * 8];           /* 128KB A frags */
    ull sred[64][8];
};
#define SMEM_BYTES ((int)sizeof(LSmem))

/* gates full-K [64 x 16cols] + LSTM cell + A-frag emit; blocks < 128 */
__device__ __forceinline__ void gates_cell_phase(GSmem* sm, const float* __restrict__ emb,
                                                 const float* __restrict__ Wih,
                                                 const float* __restrict__ Whh, int t) {
    int tid = threadIdx.x, bid = blockIdx.x;
    int j0 = bid * 4;
    if (tid < BATCH) {
        ull raw = (t == 0) ? g_initArg[tid] : __ldcg(&g_arg[(t - 1) * BATCH + tid]);
        sm->ciw[tid] = (int)(0xFFFFFFFFu - (unsigned)raw);
    }
    __syncthreads();
    int tm = tid >> 4, tn = tid & 15, m0 = tm * 4;
    ull acc0 = 0ull, acc1 = 0ull;
    int am = tid >> 2, akq = (tid & 3) * 8;
    int btn = tid & 15, bcol = (btn >> 2) * 512 + j0 + (btn & 3);
    for (int c = 0; c < GK / 32; c++) {
        int k0 = c * 32;
        {
            const float* rowp = (k0 >= WD) ? (g_h + am * H + (k0 - WD))
                                           : (emb + (size_t)sm->ciw[am] * WD + k0);
            float4 va = __ldcg((const float4*)(rowp + akq));
            float4 vb = __ldcg((const float4*)(rowp + akq + 4));
            sm->Asm[akq + 0][am] = va.x; sm->Asm[akq + 1][am] = va.y;
            sm->Asm[akq + 2][am] = va.z; sm->Asm[akq + 3][am] = va.w;
            sm->Asm[akq + 4][am] = vb.x; sm->Asm[akq + 5][am] = vb.y;
            sm->Asm[akq + 6][am] = vb.z; sm->Asm[akq + 7][am] = vb.w;
        }
#pragma unroll
        for (int p = 0; p < 2; p++) {
            int kk = (tid >> 4) + p * 16;
            int kg = k0 + kk;
            const float* wr = (kg < WD) ? (Wih + (size_t)kg * G4H) : (Whh + (size_t)(kg - WD) * G4H);
            sm->Bsm[btn][kk] = wr[bcol];
        }
        __syncthreads();
#pragma unroll
        for (int k4 = 0; k4 < 8; k4++) {
            float4 bq = *(const float4*)&sm->Bsm[tn][k4 * 4];
            float bqa[4] = {bq.x, bq.y, bq.z, bq.w};
#pragma unroll
            for (int kk = 0; kk < 4; kk++) {
                float4 av = *(const float4*)&sm->Asm[k4 * 4 + kk][m0];
                ull a01 = pack2b(av.x, av.y);
                ull a23 = pack2b(av.z, av.w);
                ull bb = pack2(bqa[kk]);
                fma2(acc0, a01, bb);
                fma2(acc1, a23, bb);
            }
        }
        __syncthreads();
    }
    sm->Csm[m0 + 0][tn] = lof(acc0);
    sm->Csm[m0 + 1][tn] = hif(acc0);
    sm->Csm[m0 + 2][tn] = lof(acc1);
    sm->Csm[m0 + 3][tn] = hif(acc1);
    __syncthreads();
    /* cell: thread -> (b, jl) */
    int b = tid >> 2, jl = tid & 3, jh = j0 + jl;
    int gid = b * H + jh;
    float gi = g_gctx[b * G4H + jh]          + sm->Csm[b][jl];
    float gf = g_gctx[b * G4H + H + jh]      + sm->Csm[b][4 + jl];
    float gg = g_gctx[b * G4H + 2 * H + jh]  + sm->Csm[b][8 + jl];
    float go = g_gctx[b * G4H + 3 * H + jh]  + sm->Csm[b][12 + jl];
    float cc = sigf(gf) * __ldcg(&g_c[gid]) + sigf(gi) * tanhf(gg);
    g_c[gid] = cc;
    float h = sigf(go) * tanhf(cc);
    g_h[gid] = h;
    int mt = b >> 4, r = b & 15, kt = jh >> 4, q = jh & 15;
    int reg = ((q >> 3) << 1) + (r >> 3);
    int lane = ((r & 7) << 2) + ((q & 7) >> 1);
    int u32i = ((mt * 32 + kt) * 32 + lane) * 8 + reg;
    __nv_bfloat16* ap = (__nv_bfloat16*)g_Aswz;
    __nv_bfloat16 bh = __float2bfloat16(h);
    ap[u32i * 2 + (q & 1)] = bh;
    ap[(u32i + 4) * 2 + (q & 1)] = __float2bfloat16(h - __bfloat162float(bh));
}

/* logits: warp covers all M=64; B read once; A staged in smem; fused argmax */
__device__ __forceinline__ void logits_phase(LSmem* sm, const float* __restrict__ bout,
                                             float* __restrict__ out, int t) {
    int tid = threadIdx.x, lane = tid & 31, w = tid >> 5;
    /* stage A fragments */
    for (int i = tid; i < 8192; i += 256)
        ((uint4*)sm->sA)[i] = __ldcg(((const uint4*)g_Aswz) + i);
    __syncthreads();
    int ntStart = (int)(((long long)NT * blockIdx.x) / GRID);
    int ntEnd   = (int)(((long long)NT * (blockIdx.x + 1)) / GRID);
    float d[4][4][4];
#pragma unroll
    for (int s = 0; s < 4; s++)
#pragma unroll
        for (int mt = 0; mt < 4; mt++)
#pragma unroll
            for (int j = 0; j < 4; j++) d[s][mt][j] = 0.f;
    for (int kt = 0; kt < 32; kt++) {
        u32 ah[4][4], al[4][4];
#pragma unroll
        for (int mt = 0; mt < 4; mt++) {
            const uint4* ap = (const uint4*)&sm->sA[((mt * 32 + kt) * 32 + lane) * 8];
            uint4 x = ap[0], y = ap[1];
            ah[mt][0] = x.x; ah[mt][1] = x.y; ah[mt][2] = x.z; ah[mt][3] = x.w;
            al[mt][0] = y.x; al[mt][1] = y.y; al[mt][2] = y.z; al[mt][3] = y.w;
        }
#pragma unroll
        for (int s = 0; s < 4; s++) {
            int nt = ntStart + w + s * 8;
            if (nt < ntEnd) {
                uint4 bv = __ldcg((const uint4*)&g_Bswz[(((size_t)nt * 32 + kt) * 32 + lane) * 4]);
#pragma unroll
                for (int mt = 0; mt < 4; mt++) {
                    mma_bf16(d[s][mt], ah[mt], bv.x, bv.y);
                    mma_bf16(d[s][mt], ah[mt], bv.z, bv.w);
                    mma_bf16(d[s][mt], al[mt], bv.x, bv.y);
                }
            }
        }
    }
    int gr = lane >> 2, c = lane & 3;
    ull keys[8];
#pragma unroll
    for (int i = 0; i < 8; i++) keys[i] = 0ull;
#pragma unroll
    for (int s = 0; s < 4; s++) {
        int nt = ntStart + w + s * 8;
        if (nt < ntEnd) {
            int col0 = nt * 8 + 2 * c;
            float2 bb = *(const float2*)(bout + col0);
#pragma unroll
            for (int mt = 0; mt < 4; mt++) {
                int rlo = mt * 16 + gr, rhi = rlo + 8;
                float v0 = d[s][mt][0] + bb.x, v1 = d[s][mt][1] + bb.y;
                float v2 = d[s][mt][2] + bb.x, v3 = d[s][mt][3] + bb.y;
                *(float2*)(out + ((size_t)rlo * TSTEPS + t) * VOCAB + col0) = make_float2(v0, v1);
                *(float2*)(out + ((size_t)rhi * TSTEPS + t) * VOCAB + col0) = make_float2(v2, v3);
                keys[mt * 2 + 0] = umax_(keys[mt * 2 + 0],
                                         umax_(amax_key(v0, col0), amax_key(v1, col0 + 1)));
                keys[mt * 2 + 1] = umax_(keys[mt * 2 + 1],
                                         umax_(amax_key(v2, col0), amax_key(v3, col0 + 1)));
            }
        }
    }
#pragma unroll
    for (int i = 0; i < 8; i++) {
        keys[i] = umax_(keys[i], __shfl_xor_sync(0xffffffffu, keys[i], 1));
        keys[i] = umax_(keys[i], __shfl_xor_sync(0xffffffffu, keys[i], 2));
    }
    if (c == 0) {
#pragma unroll
        for (int mt = 0; mt < 4; mt++) {
            sm->sred[mt * 16 + gr][w]     = keys[mt * 2 + 0];
            sm->sred[mt * 16 + 8 + gr][w] = keys[mt * 2 + 1];
        }
    }
    __syncthreads();
    if (tid < 64) {
        ull best = 0ull;
#pragma unroll
        for (int i = 0; i < 8; i++) best = umax_(best, sm->sred[tid][i]);
        atomicMax(&g_arg[t * BATCH + tid], best);
    }
}

__global__ void __launch_bounds__(256, 1) step_loop(const float* __restrict__ emb,
                                                    const float* __restrict__ Wih,
                                                    const float* __restrict__ Whh,
                                                    const float* __restrict__ bout,
                                                    float* __restrict__ out) {
    extern __shared__ char dyn[];
    unsigned ep = 0;
    for (int t = 0; t < TSTEPS; t++) {
        if (blockIdx.x < GBLK) gates_cell_phase((GSmem*)dyn, emb, Wih, Whh, t);
        gsync(GRID * (++ep));
        logits_phase((LSmem*)dyn, bout, out, t);
        if (t < TSTEPS - 1) gsync(GRID * (++ep));
    }
}

__global__ void preds_kernel(float* out) {
    int gid = blockIdx.x * 256 + threadIdx.x;
    if (gid < BATCH * TSTEPS) {
        int b = gid / TSTEPS, t = gid % TSTEPS;
        unsigned idx = 0xFFFFFFFFu - (unsigned)g_arg[t * BATCH + b];
        out[(size_t)BATCH * TSTEPS * VOCAB + gid] = (float)idx;
    }
}

extern "C" void kernel_launch(void* const* d_in, const int* in_sizes, int n_in,
                              void* d_out, int out_size) {
    const float* ehs  = (const float*)d_in[0];
    const float* enc  = (const float*)d_in[1];
    const float* emb  = (const float*)d_in[4];
    const float* W1   = (const float*)d_in[5];
    const float* W2   = (const float*)d_in[7];
    const float* W3   = (const float*)d_in[9];
    const float* Wv   = (const float*)d_in[11];
    const float* Wih  = (const float*)d_in[12];
    const float* Whh  = (const float*)d_in[13];
    const float* bih  = (const float*)d_in[14];
    const float* bhh  = (const float*)d_in[15];
    const float* Wout = (const float*)d_in[16];
    const float* bout = (const float*)d_in[17];
    float* out = (float*)d_out;

    static int attr_done = 0;
    if (!attr_done) {
        cudaFuncSetAttribute(step_loop, cudaFuncAttributeMaxDynamicSharedMemorySize, SMEM_BYTES);
        attr_done = 1;
    }

    bar_init<<<1, 1>>>();
    wout_swz<<<NT * 1024 / 256, 256>>>(Wout);
    precompute1<<<1, 512>>>(ehs, W1, W2, W3, Wv);
    scores_kernel<<<2048, 256>>>(enc);
    softmax_ctx_kernel<<<BATCH, 512>>>(enc);
    gctx_kernel<<<64, 256>>>(Wih, bih, bhh);
    step_loop<<<GRID, 256, SMEM_BYTES>>>(emb, Wih, Whh, bout, out);
    if (out_size > BATCH * TSTEPS * VOCAB)
        preds_kernel<<<(BATCH * TSTEPS + 255) / 256, 256>>>(out);
}

// round 13
// speedup vs baseline: 1.4881x; 1.4881x over previous
#include <cuda_runtime.h>
#include <cuda_bf16.h>
#include <math.h>

#define H      512
#define WD     1024
#define VOCAB  30000
#define BATCH  64
#define SEQL   256
#define TSTEPS 27
#define GK     (WD + H)
#define G4H    2048
#define KSPLIT 8
#define KRANGE (GK / KSPLIT)
#define NT     3750              /* 8-col tiles: 30000/8 */
#define GRID   148
#define GBLK   128

typedef unsigned long long ull;
typedef unsigned int u32;

__device__ float g_h[BATCH * H];
__device__ float g_c[BATCH * H];
__device__ float g_ctx[BATCH * H];
__device__ float g_gctx[BATCH * G4H];
__device__ float g_part[KSPLIT * BATCH * G4H];
__device__ float g_scores[BATCH * SEQL];
__device__ float g_u[H], g_t2[H], g_v[H];
__device__ ull   g_arg[TSTEPS * BATCH];
__device__ ull   g_initArg[BATCH];
__device__ u32   g_Aswz[4 * 32 * 32 * 8];
__device__ u32   g_Bswz[(size_t)NT * 32 * 32 * 4];
__device__ u32   g_barCnt;

__device__ __forceinline__ ull pack2(float x) {
    ull r; asm("mov.b64 %0, {%1, %1};" : "=l"(r) : "r"(__float_as_uint(x))); return r;
}
__device__ __forceinline__ void fma2(ull &acc, ull a, ull b) {
    asm("fma.rn.f32x2 %0, %1, %2, %0;" : "+l"(acc) : "l"(a), "l"(b));
}
__device__ __forceinline__ float lof(ull v) { return __uint_as_float((unsigned)v); }
__device__ __forceinline__ float hif(ull v) { return __uint_as_float((unsigned)(v >> 32)); }
__device__ __forceinline__ ull amax_key(float v, int n) {
    unsigned u = __float_as_uint(v);
    u = (u & 0x80000000u) ? ~u : (u | 0x80000000u);
    return ((ull)u << 32) | (ull)(0xFFFFFFFFu - (unsigned)n);
}
__device__ __forceinline__ ull umax_(ull a, ull b) { return a > b ? a : b; }
__device__ __forceinline__ float sigf(float x) { return 1.f / (1.f + expf(-x)); }
__device__ __forceinline__ unsigned short bf16bits(float x) {
    __nv_bfloat16 b = __float2bfloat16(x);
    return *(unsigned short*)&b;
}
__device__ __forceinline__ float bf16val(float x) {
    return __bfloat162float(__float2bfloat16(x));
}
__device__ __forceinline__ u32 packbf(float a, float b) {
    return (u32)bf16bits(a) | ((u32)bf16bits(b) << 16);
}
__device__ __forceinline__ void mma_bf16(float* d, const u32* a, u32 b0, u32 b1) {
    asm volatile("mma.sync.aligned.m16n8k16.row.col.f32.bf16.bf16.f32 "
                 "{%0,%1,%2,%3}, {%4,%5,%6,%7}, {%8,%9}, {%0,%1,%2,%3};"
                 : "+f"(d[0]), "+f"(d[1]), "+f"(d[2]), "+f"(d[3])
                 : "r"(a[0]), "r"(a[1]), "r"(a[2]), "r"(a[3]), "r"(b0), "r"(b1));
}

/* grid barrier: monotonic counter */
__device__ __forceinline__ void gsync(unsigned target) {
    __syncthreads();
    if (threadIdx.x == 0) {
        u32* cnt = &g_barCnt;
        asm volatile("fence.acq_rel.gpu;" ::: "memory");
        asm volatile("red.relaxed.gpu.add.u32 [%0], 1;" :: "l"(cnt) : "memory");
        unsigned v;
        do { asm volatile("ld.acquire.gpu.u32 %0, [%1];" : "=r"(v) : "l"(cnt) : "memory"); }
        while (v < target);
    }
    __syncthreads();
}

__global__ void bar_init() { g_barCnt = 0u; }

/* ---- one-time: Wout -> B fragments (hi/lo bf16) ---- */
__global__ void wout_swz(const float* __restrict__ Wout) {
    int gid = blockIdx.x * 256 + threadIdx.x;
    int lane = gid & 31, kt = (gid >> 5) & 31, nt = gid >> 10;
    int gr = lane >> 2, c = lane & 3;
    int n = nt * 8 + gr;
    int k0 = kt * 16 + c * 2;
    float w00 = Wout[(size_t)k0 * VOCAB + n];
    float w01 = Wout[(size_t)(k0 + 1) * VOCAB + n];
    float w10 = Wout[(size_t)(k0 + 8) * VOCAB + n];
    float w11 = Wout[(size_t)(k0 + 9) * VOCAB + n];
    uint4 v;
    v.x = packbf(w00, w01);
    v.y = packbf(w10, w11);
    v.z = packbf(w00 - bf16val(w00), w01 - bf16val(w01));
    v.w = packbf(w10 - bf16val(w10), w11 - bf16val(w11));
    *(uint4*)&g_Bswz[(size_t)gid * 4] = v;
}

/* ---- one-time: v chain, init ---- */
__global__ void precompute1(const float* __restrict__ ehs, const float* __restrict__ W1,
                            const float* __restrict__ W2, const float* __restrict__ W3,
                            const float* __restrict__ Wv) {
    int tid = threadIdx.x;
    for (int i = tid; i < BATCH * H; i += 512) { g_h[i] = ehs[i]; g_c[i] = 0.f; }
    for (int i = tid; i < TSTEPS * BATCH; i += 512) g_arg[i] = 0ull;
    if (tid < BATCH) g_initArg[tid] = (ull)(0xFFFFFFFFu - 1u);
    float acc = 0.f;
#pragma unroll 8
    for (int j = 0; j < H; j++) acc += W3[tid * H + j] * Wv[j];
    g_u[tid] = acc; __syncthreads();
    acc = 0.f;
#pragma unroll 8
    for (int j = 0; j < H; j++) acc += W2[tid * H + j] * g_u[j];
    g_t2[tid] = acc; __syncthreads();
    acc = 0.f;
#pragma unroll 8
    for (int j = 0; j < H; j++) acc += W1[tid * H + j] * g_t2[j];
    g_v[tid] = acc;
}

__global__ void scores_kernel(const float* __restrict__ enc) {
    int tid = threadIdx.x;
    int g = blockIdx.x * 8 + (tid >> 5), lane = tid & 31;
    int b = g >> 8, s = g & 255;
    const float* e = enc + ((size_t)b * SEQL + s) * H;
    float acc = 0.f;
#pragma unroll
    for (int i = 0; i < 16; i++) acc += e[lane + i * 32] * g_v[lane + i * 32];
#pragma unroll
    for (int off = 16; off; off >>= 1) acc += __shfl_xor_sync(0xffffffffu, acc, off);
    if (lane == 0) g_scores[b * SEQL + s] = acc;
}

__global__ void softmax_ctx_kernel(const float* __restrict__ enc) {
    __shared__ float ss[SEQL], red[SEQL];
    int tid = threadIdx.x, b = blockIdx.x;
    if (tid < SEQL) { float v = g_scores[b * SEQL + tid]; ss[tid] = v; red[tid] = v; }
    __syncthreads();
    for (int s = 128; s > 0; s >>= 1) { if (tid < s) red[tid] = fmaxf(red[tid], red[tid + s]); __syncthreads(); }
    float mx = red[0]; __syncthreads();
    if (tid < SEQL) { float e = expf(ss[tid] - mx); ss[tid] = e; red[tid] = e; }
    __syncthreads();
    for (int s = 128; s > 0; s >>= 1) { if (tid < s) red[tid] += red[tid + s]; __syncthreads(); }
    float inv = 1.f / red[0]; __syncthreads();
    if (tid < SEQL) ss[tid] *= inv;
    __syncthreads();
    float acc = 0.f;
    const float* eb = enc + (size_t)b * SEQL * H + tid;
#pragma unroll 16
    for (int s = 0; s < SEQL; s++) acc += ss[s] * eb[(size_t)s * H];
    g_ctx[b * H + tid] = acc;
}

__global__ void gctx_kernel(const float* __restrict__ Wih, const float* __restrict__ bih,
                            const float* __restrict__ bhh) {
    __shared__ float ctxS[8][H];
    int tid = threadIdx.x;
    int jb = blockIdx.x & 7, bt = blockIdx.x >> 3;
    for (int i = tid; i < 8 * H; i += 256)
        ctxS[i >> 9][i & (H - 1)] = g_ctx[(bt * 8 + (i >> 9)) * H + (i & (H - 1))];
    __syncthreads();
    int j = jb * 256 + tid;
    float bj = bih[j] + bhh[j];
    float acc[8];
#pragma unroll
    for (int bb = 0; bb < 8; bb++) acc[bb] = bj;
#pragma unroll 8
    for (int k = 0; k < H; k++) {
        float w = Wih[(size_t)(WD + k) * G4H + j];
#pragma unroll
        for (int bb = 0; bb < 8; bb++) acc[bb] += ctxS[bb][k] * w;
    }
#pragma unroll
    for (int bb = 0; bb < 8; bb++) g_gctx[(bt * 8 + bb) * G4H + j] = acc[bb];
}

/* ---------------- persistent step loop ---------------- */
struct SmemG { float As[32][64]; float Bs[32][128]; int ciw[64]; };
struct SmemL { ull sred[64][8]; };
union StepSmem { SmemG g; SmemL l; };

/* gates split-K (R8-proven): blocks < 128 */
__device__ __forceinline__ void gates_phase(StepSmem* sm, const float* __restrict__ emb,
                                            const float* __restrict__ Wih,
                                            const float* __restrict__ Whh, int t) {
    int tid = threadIdx.x;
    int unit = blockIdx.x;
    int jt = (unit & 15) * 128;
    int kbeg = (unit >> 4) * KRANGE;
    if (tid < BATCH) {
        ull raw = (t == 0) ? g_initArg[tid] : __ldcg(&g_arg[(t - 1) * BATCH + tid]);
        sm->g.ciw[tid] = (int)(0xFFFFFFFFu - (unsigned)raw);
    }
    __syncthreads();
    ull acc[4][4];
#pragma unroll
    for (int p = 0; p < 4; p++)
#pragma unroll
        for (int j = 0; j < 4; j++) acc[p][j] = 0ull;
    int tm = tid >> 5, tn = tid & 31, m0 = tm * 8, n0 = tn * 4;
    for (int c = 0; c < KRANGE / 32; c++) {
        int k0 = kbeg + c * 32;
        {
            int m = tid >> 2, kq = (tid & 3) * 4;
            const float* rowp = (k0 >= WD) ? (g_h + m * H + (k0 - WD))
                                           : (emb + (size_t)sm->g.ciw[m] * WD + k0);
            float4 va = __ldcg((const float4*)(rowp + kq));
            float4 vb = __ldcg((const float4*)(rowp + 16 + kq));
            sm->g.As[kq + 0][m] = va.x;  sm->g.As[kq + 1][m] = va.y;
            sm->g.As[kq + 2][m] = va.z;  sm->g.As[kq + 3][m] = va.w;
            sm->g.As[kq + 16][m] = vb.x; sm->g.As[kq + 17][m] = vb.y;
            sm->g.As[kq + 18][m] = vb.z; sm->g.As[kq + 19][m] = vb.w;
        }
#pragma unroll
        for (int r = 0; r < 4; r++) {
            int idx = tid + r * 256;
            int kk = idx >> 5, q = (idx & 31) * 4;
            int kg = k0 + kk;
            const float* wrow = (kg < WD) ? (Wih + (size_t)kg * G4H) : (Whh + (size_t)(kg - WD) * G4H);
            *(float4*)&sm->g.Bs[kk][q] = *(const float4*)(wrow + jt + q);
        }
        __syncthreads();
#pragma unroll 8
        for (int kk = 0; kk < 32; kk++) {
            ull a0 = *(const ull*)&sm->g.As[kk][m0 + 0];
            ull a1 = *(const ull*)&sm->g.As[kk][m0 + 2];
            ull a2 = *(const ull*)&sm->g.As[kk][m0 + 4];
            ull a3 = *(const ull*)&sm->g.As[kk][m0 + 6];
            float4 bv = *(const float4*)&sm->g.Bs[kk][n0];
            ull b0 = pack2(bv.x), b1 = pack2(bv.y), b2 = pack2(bv.z), b3 = pack2(bv.w);
            fma2(acc[0][0], a0, b0); fma2(acc[0][1], a0, b1);
            fma2(acc[0][2], a0, b2); fma2(acc[0][3], a0, b3);
            fma2(acc[1][0], a1, b0); fma2(acc[1][1], a1, b1);
            fma2(acc[1][2], a1, b2); fma2(acc[1][3], a1, b3);
            fma2(acc[2][0], a2, b0); fma2(acc[2][1], a2, b1);
            fma2(acc[2][2], a2, b2); fma2(acc[2][3], a2, b3);
            fma2(acc[3][0], a3, b0); fma2(acc[3][1], a3, b1);
            fma2(acc[3][2], a3, b2); fma2(acc[3][3], a3, b3);
        }
        __syncthreads();
    }
    float* outp = g_part + (size_t)(unit >> 4) * BATCH * G4H;
#pragma unroll
    for (int p = 0; p < 4; p++) {
        float4 lo4 = make_float4(lof(acc[p][0]), lof(acc[p][1]), lof(acc[p][2]), lof(acc[p][3]));
        float4 hi4 = make_float4(hif(acc[p][0]), hif(acc[p][1]), hif(acc[p][2]), hif(acc[p][3]));
        *(float4*)(outp + (size_t)(m0 + 2 * p) * G4H + jt + n0) = lo4;
        *(float4*)(outp + (size_t)(m0 + 2 * p + 1) * G4H + jt + n0) = hi4;
    }
}

/* cell (R8-proven): blocks < 128 */
__device__ __forceinline__ void cell_phase() {
    int gid = blockIdx.x * 256 + threadIdx.x;
    int b = gid >> 9, jh = gid & (H - 1);
    float gi = g_gctx[b * G4H + jh];
    float gf = g_gctx[b * G4H + H + jh];
    float gg = g_gctx[b * G4H + 2 * H + jh];
    float go = g_gctx[b * G4H + 3 * H + jh];
#pragma unroll
    for (int y = 0; y < KSPLIT; y++) {
        const float* p = g_part + (size_t)y * BATCH * G4H + b * G4H;
        gi += __ldcg(p + jh); gf += __ldcg(p + H + jh);
        gg += __ldcg(p + 2 * H + jh); go += __ldcg(p + 3 * H + jh);
    }
    float c = sigf(gf) * __ldcg(&g_c[gid]) + sigf(gi) * tanhf(gg);
    g_c[gid] = c;
    float h = sigf(go) * tanhf(c);
    g_h[gid] = h;
    int mt = b >> 4, r = b & 15, kt = jh >> 4, q = jh & 15;
    int reg = ((q >> 3) << 1) + (r >> 3);
    int lane = ((r & 7) << 2) + ((q & 7) >> 1);
    int u32i = ((mt * 32 + kt) * 32 + lane) * 8 + reg;
    __nv_bfloat16* ap = (__nv_bfloat16*)g_Aswz;
    __nv_bfloat16 bh = __float2bfloat16(h);
    ap[u32i * 2 + (q & 1)] = bh;
    ap[(u32i + 4) * 2 + (q & 1)] = __float2bfloat16(h - __bfloat162float(bh));
}

/* logits: each warp covers ALL M=64 for its tiles -> B read exactly once */
__device__ __forceinline__ void logits_phase(StepSmem* sm, const float* __restrict__ bout,
                                             float* __restrict__ out, int t) {
    int tid = threadIdx.x, lane = tid & 31, w = tid >> 5;
    int ntStart = (int)(((long long)NT * blockIdx.x) / GRID);
    int ntEnd   = (int)(((long long)NT * (blockIdx.x + 1)) / GRID);
    float d[4][4][4];
#pragma unroll
    for (int s = 0; s < 4; s++)
#pragma unroll
        for (int mt = 0; mt < 4; mt++)
#pragma unroll
            for (int j = 0; j < 4; j++) d[s][mt][j] = 0.f;
    for (int kt = 0; kt < 32; kt++) {
        u32 ah[4][4], al[4][4];
#pragma unroll
        for (int mt = 0; mt < 4; mt++) {
            const uint4* ap = (const uint4*)&g_Aswz[((mt * 32 + kt) * 32 + lane) * 8];
            uint4 x = __ldcg(ap), y = __ldcg(ap + 1);
            ah[mt][0] = x.x; ah[mt][1] = x.y; ah[mt][2] = x.z; ah[mt][3] = x.w;
            al[mt][0] = y.x; al[mt][1] = y.y; al[mt][2] = y.z; al[mt][3] = y.w;
        }
#pragma unroll
        for (int s = 0; s < 4; s++) {
            int nt = ntStart + w + s * 8;
            if (nt < ntEnd) {
                uint4 bv = *(const uint4*)&g_Bswz[(((size_t)nt * 32 + kt) * 32 + lane) * 4];
#pragma unroll
                for (int mt = 0; mt < 4; mt++) {
                    mma_bf16(d[s][mt], ah[mt], bv.x, bv.y);
                    mma_bf16(d[s][mt], ah[mt], bv.z, bv.w);
                    mma_bf16(d[s][mt], al[mt], bv.x, bv.y);
                }
            }
        }
    }
    int gr = lane >> 2, c = lane & 3;
    ull keys[8];
#pragma unroll
    for (int i = 0; i < 8; i++) keys[i] = 0ull;
#pragma unroll
    for (int s = 0; s < 4; s++) {
        int nt = ntStart + w + s * 8;
        if (nt < ntEnd) {
            int col0 = nt * 8 + 2 * c;
            float2 bb = *(const float2*)(bout + col0);
#pragma unroll
            for (int mt = 0; mt < 4; mt++) {
                int rlo = mt * 16 + gr, rhi = rlo + 8;
                float v0 = d[s][mt][0] + bb.x, v1 = d[s][mt][1] + bb.y;
                float v2 = d[s][mt][2] + bb.x, v3 = d[s][mt][3] + bb.y;
                *(float2*)(out + ((size_t)rlo * TSTEPS + t) * VOCAB + col0) = make_float2(v0, v1);
                *(float2*)(out + ((size_t)rhi * TSTEPS + t) * VOCAB + col0) = make_float2(v2, v3);
                keys[mt * 2 + 0] = umax_(keys[mt * 2 + 0],
                                         umax_(amax_key(v0, col0), amax_key(v1, col0 + 1)));
                keys[mt * 2 + 1] = umax_(keys[mt * 2 + 1],
                                         umax_(amax_key(v2, col0), amax_key(v3, col0 + 1)));
            }
        }
    }
#pragma unroll
    for (int i = 0; i < 8; i++) {
        keys[i] = umax_(keys[i], __shfl_xor_sync(0xffffffffu, keys[i], 1));
        keys[i] = umax_(keys[i], __shfl_xor_sync(0xffffffffu, keys[i], 2));
    }
    if (c == 0) {
#pragma unroll
        for (int mt = 0; mt < 4; mt++) {
            sm->l.sred[mt * 16 + gr][w]     = keys[mt * 2 + 0];
            sm->l.sred[mt * 16 + 8 + gr][w] = keys[mt * 2 + 1];
        }
    }
    __syncthreads();
    if (tid < 64) {
        ull best = 0ull;
#pragma unroll
        for (int i = 0; i < 8; i++) best = umax_(best, sm->l.sred[tid][i]);
        atomicMax(&g_arg[t * BATCH + tid], best);
    }
}

__global__ void __launch_bounds__(256, 1) step_loop(const float* __restrict__ emb,
                                                    const float* __restrict__ Wih,
                                                    const float* __restrict__ Whh,
                                                    const float* __restrict__ bout,
                                                    float* __restrict__ out) {
    __shared__ StepSmem sm;
    unsigned ep = 0;
    for (int t = 0; t < TSTEPS; t++) {
        if (blockIdx.x < GBLK) gates_phase(&sm, emb, Wih, Whh, t);
        gsync(GRID * (++ep));
        if (blockIdx.x < GBLK) cell_phase();
        gsync(GRID * (++ep));
        logits_phase(&sm, bout, out, t);
        if (t < TSTEPS - 1) gsync(GRID * (++ep));
    }
}

__global__ void preds_kernel(float* out) {
    int gid = blockIdx.x * 256 + threadIdx.x;
    if (gid < BATCH * TSTEPS) {
        int b = gid / TSTEPS, t = gid % TSTEPS;
        unsigned idx = 0xFFFFFFFFu - (unsigned)g_arg[t * BATCH + b];
        out[(size_t)BATCH * TSTEPS * VOCAB + gid] = (float)idx;
    }
}

extern "C" void kernel_launch(void* const* d_in, const int* in_sizes, int n_in,
                              void* d_out, int out_size) {
    const float* ehs  = (const float*)d_in[0];
    const float* enc  = (const float*)d_in[1];
    const float* emb  = (const float*)d_in[4];
    const float* W1   = (const float*)d_in[5];
    const float* W2   = (const float*)d_in[7];
    const float* W3   = (const float*)d_in[9];
    const float* Wv   = (const float*)d_in[11];
    const float* Wih  = (const float*)d_in[12];
    const float* Whh  = (const float*)d_in[13];
    const float* bih  = (const float*)d_in[14];
    const float* bhh  = (const float*)d_in[15];
    const float* Wout = (const float*)d_in[16];
    const float* bout = (const float*)d_in[17];
    float* out = (float*)d_out;

    bar_init<<<1, 1>>>();
    wout_swz<<<NT * 1024 / 256, 256>>>(Wout);
    precompute1<<<1, 512>>>(ehs, W1, W2, W3, Wv);
    scores_kernel<<<2048, 256>>>(enc);
    softmax_ctx_kernel<<<BATCH, 512>>>(enc);
    gctx_kernel<<<64, 256>>>(Wih, bih, bhh);
    step_loop<<<GRID, 256>>>(emb, Wih, Whh, bout, out);
    if (out_size > BATCH * TSTEPS * VOCAB)
        preds_kernel<<<(BATCH * TSTEPS + 255) / 256, 256>>>(out);
}

// round 15
// speedup vs baseline: 1.6507x; 1.1093x over previous
#include <cuda_runtime.h>
#include <cuda_bf16.h>
#include <math.h>

#define H      512
#define WD     1024
#define VOCAB  30000
#define BATCH  64
#define SEQL   256
#define TSTEPS 27
#define GK     (WD + H)
#define G4H    2048
#define KSPLIT 8
#define KRANGE (GK / KSPLIT)
#define NTPAD  3776
#define NBLK   118
#define GRID   148
#define GBLK   128

typedef unsigned long long ull;
typedef unsigned int u32;

__device__ float g_h[BATCH * H];
__device__ float g_c[BATCH * H];
__device__ float g_ctx[BATCH * H];
__device__ float g_gctx[BATCH * G4H];
__device__ float g_part[KSPLIT * BATCH * G4H];
__device__ float g_scores[BATCH * SEQL];
__device__ float g_u[H], g_t2[H], g_v[H];
__device__ ull   g_arg[TSTEPS * BATCH];
__device__ ull   g_initArg[BATCH];
__device__ u32   g_Aswz[4 * 32 * 32 * 8];
__device__ u32   g_Bswz[(size_t)NTPAD * 32 * 32 * 4];
__device__ u32   g_barCnt;

__device__ __forceinline__ ull pack2(float x) {
    ull r; asm("mov.b64 %0, {%1, %1};" : "=l"(r) : "r"(__float_as_uint(x))); return r;
}
__device__ __forceinline__ void fma2(ull &acc, ull a, ull b) {
    asm("fma.rn.f32x2 %0, %1, %2, %0;" : "+l"(acc) : "l"(a), "l"(b));
}
__device__ __forceinline__ float lof(ull v) { return __uint_as_float((unsigned)v); }
__device__ __forceinline__ float hif(ull v) { return __uint_as_float((unsigned)(v >> 32)); }
__device__ __forceinline__ ull amax_key(float v, int n) {
    unsigned u = __float_as_uint(v);
    u = (u & 0x80000000u) ? ~u : (u | 0x80000000u);
    return ((ull)u << 32) | (ull)(0xFFFFFFFFu - (unsigned)n);
}
__device__ __forceinline__ ull umax_(ull a, ull b) { return a > b ? a : b; }
__device__ __forceinline__ float sigf(float x) { return 1.f / (1.f + expf(-x)); }
__device__ __forceinline__ unsigned short bf16bits(float x) {
    __nv_bfloat16 b = __float2bfloat16(x);
    return *(unsigned short*)&b;
}
__device__ __forceinline__ float bf16val(float x) {
    return __bfloat162float(__float2bfloat16(x));
}
__device__ __forceinline__ u32 packbf(float a, float b) {
    return (u32)bf16bits(a) | ((u32)bf16bits(b) << 16);
}
__device__ __forceinline__ void mma_bf16(float* d, const u32* a, u32 b0, u32 b1) {
    asm volatile("mma.sync.aligned.m16n8k16.row.col.f32.bf16.bf16.f32 "
                 "{%0,%1,%2,%3}, {%4,%5,%6,%7}, {%8,%9}, {%0,%1,%2,%3};"
                 : "+f"(d[0]), "+f"(d[1]), "+f"(d[2]), "+f"(d[3])
                 : "r"(a[0]), "r"(a[1]), "r"(a[2]), "r"(a[3]), "r"(b0), "r"(b1));
}

/* grid barrier: monotonic counter */
__device__ __forceinline__ void gsync(unsigned target) {
    __syncthreads();
    if (threadIdx.x == 0) {
        u32* cnt = &g_barCnt;
        asm volatile("fence.acq_rel.gpu;" ::: "memory");
        asm volatile("red.relaxed.gpu.add.u32 [%0], 1;" :: "l"(cnt) : "memory");
        unsigned v;
        do { asm volatile("ld.acquire.gpu.u32 %0, [%1];" : "=r"(v) : "l"(cnt) : "memory"); }
        while (v < target);
    }
    __syncthreads();
}

/* ---- one-time: Wout -> B fragments (hi/lo bf16) ---- */
__global__ void wout_swz(const float* __restrict__ Wout) {
    int gid = blockIdx.x * 256 + threadIdx.x;
    int lane = gid & 31, kt = (gid >> 5) & 31, nt = gid >> 10;
    int gr = lane >> 2, c = lane & 3;
    int n = nt * 8 + gr;
    int k0 = kt * 16 + c * 2;
    float w00 = 0.f, w01 = 0.f, w10 = 0.f, w11 = 0.f;
    if (n < VOCAB) {
        w00 = Wout[(size_t)k0 * VOCAB + n];
        w01 = Wout[(size_t)(k0 + 1) * VOCAB + n];
        w10 = Wout[(size_t)(k0 + 8) * VOCAB + n];
        w11 = Wout[(size_t)(k0 + 9) * VOCAB + n];
    }
    uint4 v;
    v.x = packbf(w00, w01);
    v.y = packbf(w10, w11);
    v.z = packbf(w00 - bf16val(w00), w01 - bf16val(w01));
    v.w = packbf(w10 - bf16val(w10), w11 - bf16val(w11));
    *(uint4*)&g_Bswz[(size_t)gid * 4] = v;
}

/* ---- one-time: v chain, init (also resets grid-barrier counter) ---- */
__global__ void precompute1(const float* __restrict__ ehs, const float* __restrict__ W1,
                            const float* __restrict__ W2, const float* __restrict__ W3,
                            const float* __restrict__ Wv) {
    int tid = threadIdx.x;
    if (tid == 0) g_barCnt = 0u;
    for (int i = tid; i < BATCH * H; i += 512) { g_h[i] = ehs[i]; g_c[i] = 0.f; }
    for (int i = tid; i < TSTEPS * BATCH; i += 512) g_arg[i] = 0ull;
    if (tid < BATCH) g_initArg[tid] = (ull)(0xFFFFFFFFu - 1u);
    float acc = 0.f;
#pragma unroll 8
    for (int j = 0; j < H; j++) acc += W3[tid * H + j] * Wv[j];
    g_u[tid] = acc; __syncthreads();
    acc = 0.f;
#pragma unroll 8
    for (int j = 0; j < H; j++) acc += W2[tid * H + j] * g_u[j];
    g_t2[tid] = acc; __syncthreads();
    acc = 0.f;
#pragma unroll 8
    for (int j = 0; j < H; j++) acc += W1[tid * H + j] * g_t2[j];
    g_v[tid] = acc;
}

__global__ void scores_kernel(const float* __restrict__ enc) {
    int tid = threadIdx.x;
    int g = blockIdx.x * 8 + (tid >> 5), lane = tid & 31;
    int b = g >> 8, s = g & 255;
    const float* e = enc + ((size_t)b * SEQL + s) * H;
    float acc = 0.f;
#pragma unroll
    for (int i = 0; i < 16; i++) acc += e[lane + i * 32] * g_v[lane + i * 32];
#pragma unroll
    for (int off = 16; off; off >>= 1) acc += __shfl_xor_sync(0xffffffffu, acc, off);
    if (lane == 0) g_scores[b * SEQL + s] = acc;
}

__global__ void softmax_ctx_kernel(const float* __restrict__ enc) {
    __shared__ float ss[SEQL], red[SEQL];
    int tid = threadIdx.x, b = blockIdx.x;
    if (tid < SEQL) { float v = g_scores[b * SEQL + tid]; ss[tid] = v; red[tid] = v; }
    __syncthreads();
    for (int s = 128; s > 0; s >>= 1) { if (tid < s) red[tid] = fmaxf(red[tid], red[tid + s]); __syncthreads(); }
    float mx = red[0]; __syncthreads();
    if (tid < SEQL) { float e = expf(ss[tid] - mx); ss[tid] = e; red[tid] = e; }
    __syncthreads();
    for (int s = 128; s > 0; s >>= 1) { if (tid < s) red[tid] += red[tid + s]; __syncthreads(); }
    float inv = 1.f / red[0]; __syncthreads();
    if (tid < SEQL) ss[tid] *= inv;
    __syncthreads();
    float acc = 0.f;
    const float* eb = enc + (size_t)b * SEQL * H + tid;
#pragma unroll 16
    for (int s = 0; s < SEQL; s++) acc += ss[s] * eb[(size_t)s * H];
    g_ctx[b * H + tid] = acc;
}

__global__ void gctx_kernel(const float* __restrict__ Wih, const float* __restrict__ bih,
                            const float* __restrict__ bhh) {
    __shared__ float ctxS[8][H];
    int tid = threadIdx.x;
    int jb = blockIdx.x & 7, bt = blockIdx.x >> 3;
    for (int i = tid; i < 8 * H; i += 256)
        ctxS[i >> 9][i & (H - 1)] = g_ctx[(bt * 8 + (i >> 9)) * H + (i & (H - 1))];
    __syncthreads();
    int j = jb * 256 + tid;
    float bj = bih[j] + bhh[j];
    float acc[8];
#pragma unroll
    for (int bb = 0; bb < 8; bb++) acc[bb] = bj;
#pragma unroll 8
    for (int k = 0; k < H; k++) {
        float w = Wih[(size_t)(WD + k) * G4H + j];
#pragma unroll
        for (int bb = 0; bb < 8; bb++) acc[bb] += ctxS[bb][k] * w;
    }
#pragma unroll
    for (int bb = 0; bb < 8; bb++) g_gctx[(bt * 8 + bb) * G4H + j] = acc[bb];
}

/* ---------------- persistent step loop (R8-proven structure) ---------------- */
struct SmemG { float As[32][64]; float Bs[32][128]; int ciw[64]; };
struct SmemL { ull sred[64][4]; };
union StepSmem { SmemG g; SmemL l; };

__device__ __forceinline__ void gates_phase(StepSmem* sm, const float* __restrict__ emb,
                                            const float* __restrict__ Wih,
                                            const float* __restrict__ Whh, int t) {
    int tid = threadIdx.x;
    int unit = blockIdx.x;
    int jt = (unit & 15) * 128;
    int kbeg = (unit >> 4) * KRANGE;
    if (tid < BATCH) {
        ull raw = (t == 0) ? g_initArg[tid] : __ldcg(&g_arg[(t - 1) * BATCH + tid]);
        sm->g.ciw[tid] = (int)(0xFFFFFFFFu - (unsigned)raw);
    }
    __syncthreads();
    ull acc[4][4];
#pragma unroll
    for (int p = 0; p < 4; p++)
#pragma unroll
        for (int j = 0; j < 4; j++) acc[p][j] = 0ull;
    int tm = tid >> 5, tn = tid & 31, m0 = tm * 8, n0 = tn * 4;
    for (int c = 0; c < KRANGE / 32; c++) {
        int k0 = kbeg + c * 32;
        {
            int m = tid >> 2, kq = (tid & 3) * 4;
            const float* rowp = (k0 >= WD) ? (g_h + m * H + (k0 - WD))
                                           : (emb + (size_t)sm->g.ciw[m] * WD + k0);
            float4 va = __ldcg((const float4*)(rowp + kq));
            float4 vb = __ldcg((const float4*)(rowp + 16 + kq));
            sm->g.As[kq + 0][m] = va.x;  sm->g.As[kq + 1][m] = va.y;
            sm->g.As[kq + 2][m] = va.z;  sm->g.As[kq + 3][m] = va.w;
            sm->g.As[kq + 16][m] = vb.x; sm->g.As[kq + 17][m] = vb.y;
            sm->g.As[kq + 18][m] = vb.z; sm->g.As[kq + 19][m] = vb.w;
        }
#pragma unroll
        for (int r = 0; r < 4; r++) {
            int idx = tid + r * 256;
            int kk = idx >> 5, q = (idx & 31) * 4;
            int kg = k0 + kk;
            const float* wrow = (kg < WD) ? (Wih + (size_t)kg * G4H) : (Whh + (size_t)(kg - WD) * G4H);
            *(float4*)&sm->g.Bs[kk][q] = *(const float4*)(wrow + jt + q);
        }
        __syncthreads();
#pragma unroll 8
        for (int kk = 0; kk < 32; kk++) {
            ull a0 = *(const ull*)&sm->g.As[kk][m0 + 0];
            ull a1 = *(const ull*)&sm->g.As[kk][m0 + 2];
            ull a2 = *(const ull*)&sm->g.As[kk][m0 + 4];
            ull a3 = *(const ull*)&sm->g.As[kk][m0 + 6];
            float4 bv = *(const float4*)&sm->g.Bs[kk][n0];
            ull b0 = pack2(bv.x), b1 = pack2(bv.y), b2 = pack2(bv.z), b3 = pack2(bv.w);
            fma2(acc[0][0], a0, b0); fma2(acc[0][1], a0, b1);
            fma2(acc[0][2], a0, b2); fma2(acc[0][3], a0, b3);
            fma2(acc[1][0], a1, b0); fma2(acc[1][1], a1, b1);
            fma2(acc[1][2], a1, b2); fma2(acc[1][3], a1, b3);
            fma2(acc[2][0], a2, b0); fma2(acc[2][1], a2, b1);
            fma2(acc[2][2], a2, b2); fma2(acc[2][3], a2, b3);
            fma2(acc[3][0], a3, b0); fma2(acc[3][1], a3, b1);
            fma2(acc[3][2], a3, b2); fma2(acc[3][3], a3, b3);
        }
        __syncthreads();
    }
    float* outp = g_part + (size_t)(unit >> 4) * BATCH * G4H;
#pragma unroll
    for (int p = 0; p < 4; p++) {
        float4 lo4 = make_float4(lof(acc[p][0]), lof(acc[p][1]), lof(acc[p][2]), lof(acc[p][3]));
        float4 hi4 = make_float4(hif(acc[p][0]), hif(acc[p][1]), hif(acc[p][2]), hif(acc[p][3]));
        *(float4*)(outp + (size_t)(m0 + 2 * p) * G4H + jt + n0) = lo4;
        *(float4*)(outp + (size_t)(m0 + 2 * p + 1) * G4H + jt + n0) = hi4;
    }
}

__device__ __forceinline__ void cell_phase() {
    int gid = blockIdx.x * 256 + threadIdx.x;
    int b = gid >> 9, jh = gid & (H - 1);
    float gi = g_gctx[b * G4H + jh];
    float gf = g_gctx[b * G4H + H + jh];
    float gg = g_gctx[b * G4H + 2 * H + jh];
    float go = g_gctx[b * G4H + 3 * H + jh];
#pragma unroll
    for (int y = 0; y < KSPLIT; y++) {
        const float* p = g_part + (size_t)y * BATCH * G4H + b * G4H;
        gi += __ldcg(p + jh); gf += __ldcg(p + H + jh);
        gg += __ldcg(p + 2 * H + jh); go += __ldcg(p + 3 * H + jh);
    }
    float c = sigf(gf) * __ldcg(&g_c[gid]) + sigf(gi) * tanhf(gg);
    g_c[gid] = c;
    float h = sigf(go) * tanhf(c);
    g_h[gid] = h;
    int mt = b >> 4, r = b & 15, kt = jh >> 4, q = jh & 15;
    int reg = ((q >> 3) << 1) + (r >> 3);
    int lane = ((r & 7) << 2) + ((q & 7) >> 1);
    int u32i = ((mt * 32 + kt) * 32 + lane) * 8 + reg;
    __nv_bfloat16* ap = (__nv_bfloat16*)g_Aswz;
    __nv_bfloat16 bh = __float2bfloat16(h);
    ap[u32i * 2 + (q & 1)] = bh;
    ap[(u32i + 4) * 2 + (q & 1)] = __float2bfloat16(h - __bfloat162float(bh));
}

/* logits (R8-proven mapping): warp = 2 m-tiles x 8 n-tiles; blocks < NBLK */
__device__ __forceinline__ void logits_phase(StepSmem* sm, const float* __restrict__ bout,
                                             float* __restrict__ out, int t) {
    int tid = threadIdx.x, lane = tid & 31, w = tid >> 5;
    int mhalf = w >> 2, nquad = w & 3;
    int ntbase = blockIdx.x * 32 + nquad * 8;
    float d[2][8][4];
#pragma unroll
    for (int mt = 0; mt < 2; mt++)
#pragma unroll
        for (int n = 0; n < 8; n++)
#pragma unroll
            for (int j = 0; j < 4; j++) d[mt][n][j] = 0.f;
    for (int kt = 0; kt < 32; kt++) {
        u32 ah[2][4], al[2][4];
#pragma unroll
        for (int mt = 0; mt < 2; mt++) {
            const uint4* ap = (const uint4*)&g_Aswz[(((mhalf * 2 + mt) * 32 + kt) * 32 + lane) * 8];
            uint4 x = __ldcg(ap), y = __ldcg(ap + 1);
            ah[mt][0] = x.x; ah[mt][1] = x.y; ah[mt][2] = x.z; ah[mt][3] = x.w;
            al[mt][0] = y.x; al[mt][1] = y.y; al[mt][2] = y.z; al[mt][3] = y.w;
        }
#pragma unroll
        for (int ntl = 0; ntl < 8; ntl++) {
            uint4 bv = *(const uint4*)&g_Bswz[(size_t)(((ntbase + ntl) * 32 + kt) * 32 + lane) * 4];
#pragma unroll
            for (int mt = 0; mt < 2; mt++) {
                mma_bf16(d[mt][ntl], ah[mt], bv.x, bv.y);
                mma_bf16(d[mt][ntl], ah[mt], bv.z, bv.w);
                mma_bf16(d[mt][ntl], al[mt], bv.x, bv.y);
            }
        }
    }
    int gr = lane >> 2, c = lane & 3;
    int mbase = mhalf * 32;
    ull keys[4] = {0ull, 0ull, 0ull, 0ull};
#pragma unroll
    for (int ntl = 0; ntl < 8; ntl++) {
        int col0 = (ntbase + ntl) * 8 + 2 * c;
        bool ok = col0 < VOCAB;
        float2 bb = ok ? *(const float2*)(bout + col0) : make_float2(0.f, 0.f);
#pragma unroll
        for (int mt = 0; mt < 2; mt++) {
            int rlo = mbase + mt * 16 + gr, rhi = rlo + 8;
            float v0 = d[mt][ntl][0] + bb.x, v1 = d[mt][ntl][1] + bb.y;
            float v2 = d[mt][ntl][2] + bb.x, v3 = d[mt][ntl][3] + bb.y;
            if (ok) {
                *(float2*)(out + ((size_t)rlo * TSTEPS + t) * VOCAB + col0) = make_float2(v0, v1);
                *(float2*)(out + ((size_t)rhi * TSTEPS + t) * VOCAB + col0) = make_float2(v2, v3);
                ull k0 = umax_(amax_key(v0, col0), amax_key(v1, col0 + 1));
                ull k1 = umax_(amax_key(v2, col0), amax_key(v3, col0 + 1));
                keys[mt * 2 + 0] = umax_(keys[mt * 2 + 0], k0);
                keys[mt * 2 + 1] = umax_(keys[mt * 2 + 1], k1);
            }
        }
    }
#pragma unroll
    for (int i = 0; i < 4; i++) {
        keys[i] = umax_(keys[i], __shfl_xor_sync(0xffffffffu, keys[i], 1));
        keys[i] = umax_(keys[i], __shfl_xor_sync(0xffffffffu, keys[i], 2));
    }
    if (c == 0) {
#pragma unroll
        for (int mt = 0; mt < 2; mt++) {
            sm->l.sred[mbase + mt * 16 + gr][nquad] = keys[mt * 2 + 0];
            sm->l.sred[mbase + mt * 16 + 8 + gr][nquad] = keys[mt * 2 + 1];
        }
    }
    __syncthreads();
    if (tid < 64) {
        ull best = umax_(umax_(sm->l.sred[tid][0], sm->l.sred[tid][1]),
                         umax_(sm->l.sred[tid][2], sm->l.sred[tid][3]));
        atomicMax(&g_arg[t * BATCH + tid], best);
    }
}

__global__ void __launch_bounds__(256, 1) step_loop(const float* __restrict__ emb,
                                                    const float* __restrict__ Wih,
                                                    const float* __restrict__ Whh,
                                                    const float* __restrict__ bout,
                                                    float* __restrict__ out) {
    __shared__ StepSmem sm;
    unsigned ep = 0;
    for (int t = 0; t < TSTEPS; t++) {
        if (blockIdx.x < GBLK) gates_phase(&sm, emb, Wih, Whh, t);
        gsync(GRID * (++ep));
        if (blockIdx.x < GBLK) cell_phase();
        gsync(GRID * (++ep));
        if (blockIdx.x < NBLK) logits_phase(&sm, bout, out, t);
        if (t < TSTEPS - 1) gsync(GRID * (++ep));
    }
}

__global__ void preds_kernel(float* out) {
    int gid = blockIdx.x * 256 + threadIdx.x;
    if (gid < BATCH * TSTEPS) {
        int b = gid / TSTEPS, t = gid % TSTEPS;
        unsigned idx = 0xFFFFFFFFu - (unsigned)g_arg[t * BATCH + b];
        out[(size_t)BATCH * TSTEPS * VOCAB + gid] = (float)idx;
    }
}

extern "C" void kernel_launch(void* const* d_in, const int* in_sizes, int n_in,
                              void* d_out, int out_size) {
    const float* ehs  = (const float*)d_in[0];
    const float* enc  = (const float*)d_in[1];
    const float* emb  = (const float*)d_in[4];
    const float* W1   = (const float*)d_in[5];
    const float* W2   = (const float*)d_in[7];
    const float* W3   = (const float*)d_in[9];
    const float* Wv   = (const float*)d_in[11];
    const float* Wih  = (const float*)d_in[12];
    const float* Whh  = (const float*)d_in[13];
    const float* bih  = (const float*)d_in[14];
    const float* bhh  = (const float*)d_in[15];
    const float* Wout = (const float*)d_in[16];
    const float* bout = (const float*)d_in[17];
    float* out = (float*)d_out;

    /* launch order chosen so step_loop is launch #6 -> captured by ncu -s 5 -c 1 */
    wout_swz<<<NTPAD * 1024 / 256, 256>>>(Wout);
    precompute1<<<1, 512>>>(ehs, W1, W2, W3, Wv);   /* also resets g_barCnt */
    scores_kernel<<<2048, 256>>>(enc);
    softmax_ctx_kernel<<<BATCH, 512>>>(enc);
    gctx_kernel<<<64, 256>>>(Wih, bih, bhh);
    step_loop<<<GRID, 256>>>(emb, Wih, Whh, bout, out);
    if (out_size > BATCH * TSTEPS * VOCAB)
        preds_kernel<<<(BATCH * TSTEPS + 255) / 256, 256>>>(out);
}